// round 1
// baseline (speedup 1.0000x reference)
#include <cuda_runtime.h>
#include <math.h>

#define NB 8
#define LW 512
#define LE 64
#define SS 576            // LW + LE
#define HH 1024
#define NHEAD 16
#define HD 64
#define MTOT (NB*SS)      // 4608

// ---------------- scratch (device globals; no allocation) ----------------
__device__ float g_x  [ (long)MTOT * HH ];
__device__ float g_q  [ (long)MTOT * HH ];
__device__ float g_k  [ (long)MTOT * HH ];
__device__ float g_v  [ (long)MTOT * HH ];
__device__ float g_ctx[ (long)MTOT * HH ];
__device__ float g_y  [ (long)MTOT * HH ];

// ---------------- concat word/entity into g_x [B,S,H] ----------------
__global__ void concat_kernel(const float* __restrict__ w,
                              const float* __restrict__ e) {
    long i = (long)blockIdx.x * blockDim.x + threadIdx.x;   // float4 index
    long n4 = (long)MTOT * HH / 4;
    if (i >= n4) return;
    long idx = i * 4;
    int b = (int)(idx / ((long)SS * HH));
    long rem = idx % ((long)SS * HH);
    int s = (int)(rem / HH);
    int h = (int)(rem % HH);
    float4 val;
    if (s < LW) val = *(const float4*)&w[((long)b * LW + s) * HH + h];
    else        val = *(const float4*)&e[((long)b * LE + (s - LW)) * HH + h];
    *(float4*)&g_x[idx] = val;
}

// ---------------- fp32 tiled GEMM: C = A[M,K]*W[K,N] + bias (+resid) ----------
// BM=BN=128, BK=16, 256 threads, 8x8 microtile per thread
template<bool RESID>
__global__ __launch_bounds__(256)
void gemm_kernel(const float* __restrict__ A, const float* __restrict__ W,
                 const float* __restrict__ bias, const float* __restrict__ resid,
                 float* __restrict__ C, int M, int N, int K) {
    __shared__ float As[16][132];   // transposed A tile, padded (132*4 % 16 == 0)
    __shared__ float Bs[16][128];

    int tid = threadIdx.x;
    int bm = blockIdx.y * 128;
    int bn = blockIdx.x * 128;
    int ty = tid / 16, tx = tid % 16;

    float acc[8][8];
    #pragma unroll
    for (int i = 0; i < 8; i++)
        #pragma unroll
        for (int j = 0; j < 8; j++) acc[i][j] = 0.f;

    int arow = tid / 4;          // 0..63 -> rows arow, arow+64
    int acol = (tid % 4) * 4;    // 0,4,8,12
    int brow = tid / 32;         // 0..7 -> rows brow, brow+8
    int bcol = (tid % 32) * 4;   // 0..124

    for (int k0 = 0; k0 < K; k0 += 16) {
        #pragma unroll
        for (int r = 0; r < 2; r++) {
            int row = arow + r * 64;
            float4 a = *(const float4*)&A[(long)(bm + row) * K + k0 + acol];
            As[acol + 0][row] = a.x;
            As[acol + 1][row] = a.y;
            As[acol + 2][row] = a.z;
            As[acol + 3][row] = a.w;
        }
        #pragma unroll
        for (int r = 0; r < 2; r++) {
            int row = brow + r * 8;
            *(float4*)&Bs[row][bcol] =
                *(const float4*)&W[(long)(k0 + row) * N + bn + bcol];
        }
        __syncthreads();
        #pragma unroll
        for (int kk = 0; kk < 16; kk++) {
            float a[8], b[8];
            *(float4*)&a[0] = *(float4*)&As[kk][ty * 8];
            *(float4*)&a[4] = *(float4*)&As[kk][ty * 8 + 4];
            *(float4*)&b[0] = *(float4*)&Bs[kk][tx * 8];
            *(float4*)&b[4] = *(float4*)&Bs[kk][tx * 8 + 4];
            #pragma unroll
            for (int i = 0; i < 8; i++)
                #pragma unroll
                for (int j = 0; j < 8; j++)
                    acc[i][j] += a[i] * b[j];
        }
        __syncthreads();
    }

    #pragma unroll
    for (int i = 0; i < 8; i++) {
        long m = bm + ty * 8 + i;
        #pragma unroll
        for (int j = 0; j < 8; j += 4) {
            int n = bn + tx * 8 + j;
            float4 bi = *(const float4*)&bias[n];
            float4 o;
            o.x = acc[i][j + 0] + bi.x;
            o.y = acc[i][j + 1] + bi.y;
            o.z = acc[i][j + 2] + bi.z;
            o.w = acc[i][j + 3] + bi.w;
            if (RESID) {
                float4 r = *(const float4*)&resid[m * N + n];
                o.x += r.x; o.y += r.y; o.z += r.z; o.w += r.w;
            }
            *(float4*)&C[m * N + n] = o;
        }
    }
}

// ---------------- attention: per (b, head, 8-query tile) -------------------
// smem: qs 2KB + kts 17.4KB + sc 18.4KB  < 48KB static
#define QT 8
#define NQT (SS / QT)     // 72
__global__ __launch_bounds__(256)
void attn_kernel(const float* __restrict__ mask) {
    int idx = blockIdx.x;
    int t = idx % NQT;  idx /= NQT;
    int h = idx % NHEAD;
    int b = idx / NHEAD;
    int q0 = t * QT;

    __shared__ float qs[QT][64];
    __shared__ float kts[64][68];          // K tile, padded row stride
    __shared__ float sc[QT][SS];

    int tid = threadIdx.x;
    const float* qbase = g_q + (long)b * SS * HH + h * HD;
    const float* kbase = g_k + (long)b * SS * HH + h * HD;
    const float* vbase = g_v + (long)b * SS * HH + h * HD;

    // load Q tile: 8*64 floats = 128 float4
    if (tid < 128) {
        int r = tid / 16;
        int c = (tid % 16) * 4;
        *(float4*)&qs[r][c] = *(const float4*)&qbase[(long)(q0 + r) * HH + c];
    }
    __syncthreads();

    // pass 1: scores (loop over 9 key tiles of 64)
    int qi = tid / 64;     // 0..3 -> rows qi, qi+4
    int kj = tid % 64;
    for (int kt = 0; kt < 9; kt++) {
        #pragma unroll
        for (int r4 = 0; r4 < 4; r4++) {
            int e = tid + r4 * 256;        // float4 index 0..1023
            int row = e / 16;
            int col = (e % 16) * 4;
            *(float4*)&kts[row][col] =
                *(const float4*)&kbase[(long)(kt * 64 + row) * HH + col];
        }
        __syncthreads();
        float mk = mask[b * SS + kt * 64 + kj];
        #pragma unroll
        for (int qq = 0; qq < 2; qq++) {
            int q = qi + qq * 4;
            float s = 0.f;
            #pragma unroll
            for (int d4 = 0; d4 < 16; d4++) {
                float4 a = *(const float4*)&qs[q][d4 * 4];
                float4 kv = *(const float4*)&kts[kj][d4 * 4];
                s += a.x * kv.x + a.y * kv.y + a.z * kv.z + a.w * kv.w;
            }
            sc[q][kt * 64 + kj] = s * 0.125f + mk;
        }
        __syncthreads();
    }

    // pass 2: softmax, one warp per row
    {
        int w = tid / 32, lane = tid % 32;
        if (w < QT) {
            int r = w;
            float m = -1e30f;
            for (int j = lane; j < SS; j += 32) m = fmaxf(m, sc[r][j]);
            #pragma unroll
            for (int o = 16; o > 0; o >>= 1)
                m = fmaxf(m, __shfl_xor_sync(0xffffffff, m, o));
            float sum = 0.f;
            for (int j = lane; j < SS; j += 32) {
                float p = __expf(sc[r][j] - m);
                sc[r][j] = p;
                sum += p;
            }
            #pragma unroll
            for (int o = 16; o > 0; o >>= 1)
                sum += __shfl_xor_sync(0xffffffff, sum, o);
            float inv = 1.0f / sum;
            for (int j = lane; j < SS; j += 32) sc[r][j] *= inv;
        }
    }
    __syncthreads();

    // pass 3: ctx = probs @ V
    {
        int d = tid % 64;
        int qg = tid / 64;   // rows qg, qg+4
        float acc0 = 0.f, acc1 = 0.f;
        for (int j = 0; j < SS; j++) {
            float v = vbase[(long)j * HH + d];
            acc0 += sc[qg][j] * v;
            acc1 += sc[qg + 4][j] * v;
        }
        float* ctxbase = g_ctx + ((long)b * SS + q0) * HH + h * HD;
        ctxbase[(long)qg * HH + d] = acc0;
        ctxbase[(long)(qg + 4) * HH + d] = acc1;
    }
}

// ---------------- LayerNorm + output split ordering ----------------
__global__ __launch_bounds__(256)
void ln_out_kernel(const float* __restrict__ ln_w, const float* __restrict__ ln_b,
                   float* __restrict__ out) {
    int row = blockIdx.x;          // 0..MTOT-1
    int b = row / SS, s = row % SS;
    const float* y = g_y + (long)row * HH;
    int tid = threadIdx.x;

    float4 v = *(const float4*)&y[tid * 4];
    float sum = v.x + v.y + v.z + v.w;
    float sq  = v.x * v.x + v.y * v.y + v.z * v.z + v.w * v.w;

    __shared__ float s_sum[8], s_sq[8], s_stats[2];
    int w = tid / 32, lane = tid % 32;
    #pragma unroll
    for (int o = 16; o > 0; o >>= 1) {
        sum += __shfl_xor_sync(0xffffffff, sum, o);
        sq  += __shfl_xor_sync(0xffffffff, sq,  o);
    }
    if (lane == 0) { s_sum[w] = sum; s_sq[w] = sq; }
    __syncthreads();
    if (tid == 0) {
        float ts = 0.f, tq = 0.f;
        #pragma unroll
        for (int i = 0; i < 8; i++) { ts += s_sum[i]; tq += s_sq[i]; }
        float mean = ts * (1.0f / HH);
        float var  = tq * (1.0f / HH) - mean * mean;
        s_stats[0] = mean;
        s_stats[1] = rsqrtf(var + 1e-12f);
    }
    __syncthreads();
    float mean = s_stats[0], inv = s_stats[1];

    long dst;
    if (s < LW) dst = ((long)b * LW + s) * HH;
    else        dst = (long)NB * LW * HH + ((long)b * LE + (s - LW)) * HH;

    float4 w4 = *(const float4*)&ln_w[tid * 4];
    float4 b4 = *(const float4*)&ln_b[tid * 4];
    float4 o;
    o.x = (v.x - mean) * inv * w4.x + b4.x;
    o.y = (v.y - mean) * inv * w4.y + b4.y;
    o.z = (v.z - mean) * inv * w4.z + b4.z;
    o.w = (v.w - mean) * inv * w4.w + b4.w;
    *(float4*)&out[dst + tid * 4] = o;
}

// ---------------- launch ----------------
extern "C" void kernel_launch(void* const* d_in, const int* in_sizes, int n_in,
                              void* d_out, int out_size) {
    const float* word = (const float*)d_in[0];
    const float* ent  = (const float*)d_in[1];
    const float* mask = (const float*)d_in[2];
    const float* Wq   = (const float*)d_in[3];
    const float* bq   = (const float*)d_in[4];
    const float* Wk   = (const float*)d_in[5];
    const float* bk   = (const float*)d_in[6];
    const float* Wv   = (const float*)d_in[7];
    const float* bv   = (const float*)d_in[8];
    const float* Wo   = (const float*)d_in[9];
    const float* bo   = (const float*)d_in[10];
    const float* lnw  = (const float*)d_in[11];
    const float* lnb  = (const float*)d_in[12];
    float* out = (float*)d_out;

    float *px, *pq, *pk, *pv, *pc, *py;
    cudaGetSymbolAddress((void**)&px, g_x);
    cudaGetSymbolAddress((void**)&pq, g_q);
    cudaGetSymbolAddress((void**)&pk, g_k);
    cudaGetSymbolAddress((void**)&pv, g_v);
    cudaGetSymbolAddress((void**)&pc, g_ctx);
    cudaGetSymbolAddress((void**)&py, g_y);

    // 1) concat
    {
        long n4 = (long)MTOT * HH / 4;
        int blocks = (int)((n4 + 255) / 256);
        concat_kernel<<<blocks, 256>>>(word, ent);
    }

    // 2) Q/K/V projections
    {
        dim3 grid(HH / 128, MTOT / 128);
        gemm_kernel<false><<<grid, 256>>>(px, Wq, bq, nullptr, pq, MTOT, HH, HH);
        gemm_kernel<false><<<grid, 256>>>(px, Wk, bk, nullptr, pk, MTOT, HH, HH);
        gemm_kernel<false><<<grid, 256>>>(px, Wv, bv, nullptr, pv, MTOT, HH, HH);
    }

    // 3) attention
    {
        int blocks = NB * NHEAD * NQT;   // 9216
        attn_kernel<<<blocks, 256>>>(mask);
    }

    // 4) output projection + bias + residual
    {
        dim3 grid(HH / 128, MTOT / 128);
        gemm_kernel<true><<<grid, 256>>>(pc, Wo, bo, px, py, MTOT, HH, HH);
    }

    // 5) LayerNorm + split write
    {
        ln_out_kernel<<<MTOT, 256>>>(lnw, lnb, out);
    }
}